// round 16
// baseline (speedup 1.0000x reference)
#include <cuda_runtime.h>
#include <cuda_bf16.h>

// ---------------- problem constants ----------------
#define ZD 21
#define YD 256
#define XD 256
#define BD 2
#define CIN 16
#define C1 32
#define C2 64
#define GRID_SZ (BD * ZD * YD * XD)   // 2,752,512
#define N_MAX 400000
#define BN_EPS 1e-3f

typedef unsigned long long u64;

// ---------------- device scratch ----------------
__device__ int   g_grid[GRID_SZ];
__device__ float g_f1[N_MAX * C1];
__device__ u64   g_W1p[27 * 8 * 32];    // (W1[k][2p][ch], W1[k][2p+1][ch])
__device__ u64   g_W2p[27 * 16 * 64];   // (W2[k][2p][ch], W2[k][2p+1][ch])
__device__ float g_sc1[C1], g_sh1[C1];  // folded BN: y = relu(x*sc + sh)
__device__ float g_sc2[C2], g_sh2[C2];

// ---------------- helpers ----------------
__device__ __forceinline__ u64 pack2(float a, float b) {
    u64 r; asm("mov.b64 %0, {%1, %2};" : "=l"(r) : "f"(a), "f"(b)); return r;
}
__device__ __forceinline__ void ffma2(u64& acc, u64 a, u64 b) {
    asm("fma.rn.f32x2 %0, %1, %2, %0;" : "+l"(acc) : "l"(a), "l"(b));
}
__device__ __forceinline__ float2 unpack2(u64 p) {
    float2 r; asm("mov.b64 {%0, %1}, %2;" : "=f"(r.x), "=f"(r.y) : "l"(p)); return r;
}

__global__ void reset_grid_kernel() {
    int i = blockIdx.x * blockDim.x + threadIdx.x;
    if (i < GRID_SZ / 4) ((int4*)g_grid)[i] = make_int4(-1, -1, -1, -1);
}

__global__ void scatter_kernel(const int* __restrict__ coors, int n) {
    int i = blockIdx.x * blockDim.x + threadIdx.x;
    if (i >= n) return;
    int4 c = ((const int4*)coors)[i];
    int lin = ((c.x * ZD + c.y) * YD + c.z) * XD + c.w;
    g_grid[lin] = i;
}

// Pre-pack weights into cc-pair u64 layout + fold BN into scale/shift.
__global__ void prep_w1_kernel(const float* __restrict__ W1,
                               const float* __restrict__ g1, const float* __restrict__ b1,
                               const float* __restrict__ m1, const float* __restrict__ v1) {
    int i = blockIdx.x * blockDim.x + threadIdx.x;  // 27*8*32 = 6912
    if (i < 27 * 8 * 32) {
        int ch = i & 31, p = (i >> 5) & 7, k = i >> 8;
        const float* base = W1 + k * (CIN * C1);
        g_W1p[i] = pack2(base[(2 * p) * C1 + ch], base[(2 * p + 1) * C1 + ch]);
    }
    if (i < C1) {
        float sc = g1[i] * rsqrtf(v1[i] + BN_EPS);
        g_sc1[i] = sc;
        g_sh1[i] = b1[i] - m1[i] * sc;
    }
}
__global__ void prep_w2_kernel(const float* __restrict__ W2,
                               const float* __restrict__ g2, const float* __restrict__ b2,
                               const float* __restrict__ m2, const float* __restrict__ v2) {
    int i = blockIdx.x * blockDim.x + threadIdx.x;  // 27*16*64 = 27648
    if (i < 27 * 16 * 64) {
        int ch = i & 63, p = (i >> 6) & 15, k = i >> 10;
        const float* base = W2 + k * (C1 * C2);
        g_W2p[i] = pack2(base[(2 * p) * C2 + ch], base[(2 * p + 1) * C2 + ch]);
    }
    if (i < C2) {
        float sc = g2[i] * rsqrtf(v2[i] + BN_EPS);
        g_sc2[i] = sc;
        g_sh2[i] = b2[i] - m2[i] * sc;
    }
}

// ===================== conv1: SubMConv3d k=3 pad=1, 16 -> 32 =====================
// Block owns 128 voxels. k-loop is block-uniform: threads 0-127 look up their
// voxel's neighbor for offset k and warp-compact active pairs to smem; then all
// 8 warps process the pair list with W1[k] register-resident (lane = out ch).
// Accumulation into smem tile (race-free: distinct voxels within a k, k's
// barrier-serialized).
__global__ void __launch_bounds__(256)
conv1_kernel(const float* __restrict__ feat,
             const int*   __restrict__ coors,
             int n) {
    __shared__ float    oacc[128][C1];   // 16KB
    __shared__ unsigned pairs[128];      // (row<<7)|lvox
    __shared__ int      cnts[4];

    int t    = threadIdx.x;
    int lane = t & 31;
    int warp = t >> 5;
    int base = blockIdx.x * 128;

    int4 c = make_int4(0, 0, 0, 0);
    bool valid = false;
    if (t < 128 && base + t < n) {
        c = __ldg((const int4*)coors + base + t);
        valid = true;
    }

    for (int j = t; j < 128 * C1 / 4; j += 256)
        ((float4*)oacc)[j] = make_float4(0.f, 0.f, 0.f, 0.f);
    __syncthreads();

    for (int k = 0; k < 27; k++) {
        // --- phase A: lookup + warp-compact (threads 0..127) ---
        if (t < 128) {
            int row = -1;
            if (valid) {
                int zz = c.y + k / 9 - 1;
                int yy = c.z + (k / 3) % 3 - 1;
                int xx = c.w + k % 3 - 1;
                if (zz >= 0 && zz < ZD && yy >= 0 && yy < YD && xx >= 0 && xx < XD)
                    row = g_grid[((c.x * ZD + zz) * YD + yy) * XD + xx];
            }
            unsigned bal = __ballot_sync(0xffffffffu, row >= 0);
            if (row >= 0) {
                int pos = __popc(bal & ((1u << lane) - 1u));
                pairs[warp * 32 + pos] = ((unsigned)row << 7) | (unsigned)t;
            }
            if (lane == 0) cnts[warp] = __popc(bal);
        }
        __syncthreads();

        int total = cnts[0] + cnts[1] + cnts[2] + cnts[3];
        if (total > 0) {
            // W1[k] register-resident: lane owns channel `lane`
            const u64* Wk = g_W1p + k * (8 * 32) + lane;
            u64 w[8];
#pragma unroll
            for (int p = 0; p < 8; p++) w[p] = __ldg(Wk + p * 32);

            // 8 warps stride the pair lists
            for (int q = 0; q < 4; q++) {
                int nq = cnts[q];
                for (int j = warp; j < nq; j += 8) {
                    unsigned pm = pairs[q * 32 + j];
                    int row = pm >> 7;
                    int lv  = pm & 127;
                    const ulonglong2* f = (const ulonglong2*)(feat + row * CIN);
                    u64 acc = 0ull;
                    ulonglong2 q0 = __ldg(f + 0);
                    ulonglong2 q1 = __ldg(f + 1);
                    ulonglong2 q2 = __ldg(f + 2);
                    ulonglong2 q3 = __ldg(f + 3);
                    ffma2(acc, q0.x, w[0]); ffma2(acc, q0.y, w[1]);
                    ffma2(acc, q1.x, w[2]); ffma2(acc, q1.y, w[3]);
                    ffma2(acc, q2.x, w[4]); ffma2(acc, q2.y, w[5]);
                    ffma2(acc, q3.x, w[6]); ffma2(acc, q3.y, w[7]);
                    float2 s = unpack2(acc);
                    oacc[lv][lane] += s.x + s.y;
                }
            }
        }
        __syncthreads();
    }

    // --- epilogue: folded BN + ReLU; thread owns half a voxel (16 ch) ---
    {
        int lv = t >> 1;
        int h  = t & 1;
        int i  = base + lv;
        if (i < n) {
            const float4* sc = (const float4*)(g_sc1 + h * 16);
            const float4* sh = (const float4*)(g_sh1 + h * 16);
            float4* dst = (float4*)(g_f1 + i * C1 + h * 16);
#pragma unroll
            for (int j = 0; j < 4; j++) {
                float4 x = *(const float4*)&oacc[lv][h * 16 + 4 * j];
                float4 s = __ldg(sc + j), o = __ldg(sh + j);
                float4 r;
                r.x = fmaxf(fmaf(x.x, s.x, o.x), 0.f);
                r.y = fmaxf(fmaf(x.y, s.y, o.y), 0.f);
                r.z = fmaxf(fmaf(x.z, s.z, o.z), 0.f);
                r.w = fmaxf(fmaf(x.w, s.w, o.w), 0.f);
                dst[j] = r;
            }
        }
    }
}

// ===================== conv2: SparseConv3d k=3 s=2 pad=(0,1,1), 32 -> 64 =========
// Same structure; warps split into channel halves (h = warp&1, ch = lane+32h),
// pair stride 4 per half.
__global__ void __launch_bounds__(256)
conv2_kernel(const int* __restrict__ ocoors,
             float*     __restrict__ out,
             int m) {
    __shared__ float    oacc[128][C2];   // 32KB
    __shared__ unsigned pairs[128];
    __shared__ int      cnts[4];

    int t    = threadIdx.x;
    int lane = t & 31;
    int warp = t >> 5;
    int base = blockIdx.x * 128;

    int4 c = make_int4(0, 0, 0, 0);
    bool valid = false;
    if (t < 128 && base + t < m) {
        c = __ldg((const int4*)ocoors + base + t);
        valid = true;
    }

    for (int j = t; j < 128 * C2 / 4; j += 256)
        ((float4*)oacc)[j] = make_float4(0.f, 0.f, 0.f, 0.f);
    __syncthreads();

    int h  = warp & 1;          // channel half
    int s  = warp >> 1;         // pair stride offset (0..3)
    int ch = lane + h * 32;

    for (int k = 0; k < 27; k++) {
        if (t < 128) {
            int row = -1;
            if (valid) {
                int zz = c.y * 2 + k / 9;            // pad 0 in z
                int yy = c.z * 2 - 1 + (k / 3) % 3;  // pad 1 in y
                int xx = c.w * 2 - 1 + k % 3;        // pad 1 in x
                if (zz < ZD && yy >= 0 && yy < YD && xx >= 0 && xx < XD)
                    row = g_grid[((c.x * ZD + zz) * YD + yy) * XD + xx];
            }
            unsigned bal = __ballot_sync(0xffffffffu, row >= 0);
            if (row >= 0) {
                int pos = __popc(bal & ((1u << lane) - 1u));
                pairs[warp * 32 + pos] = ((unsigned)row << 7) | (unsigned)t;
            }
            if (lane == 0) cnts[warp] = __popc(bal);
        }
        __syncthreads();

        int total = cnts[0] + cnts[1] + cnts[2] + cnts[3];
        if (total > 0) {
            // W2[k] half register-resident: lane owns channel `ch`
            const u64* Wk = g_W2p + k * (16 * 64) + ch;
            u64 w[16];
#pragma unroll
            for (int p = 0; p < 16; p++) w[p] = __ldg(Wk + p * 64);

            for (int q = 0; q < 4; q++) {
                int nq = cnts[q];
                for (int j = s; j < nq; j += 4) {
                    unsigned pm = pairs[q * 32 + j];
                    int row = pm >> 7;
                    int lv  = pm & 127;
                    const ulonglong2* f = (const ulonglong2*)(g_f1 + row * C1);
                    u64 acc = 0ull;
#pragma unroll
                    for (int u = 0; u < 4; u++) {
                        ulonglong2 qa = __ldg(f + 2 * u);
                        ulonglong2 qb = __ldg(f + 2 * u + 1);
                        ffma2(acc, qa.x, w[4 * u + 0]);
                        ffma2(acc, qa.y, w[4 * u + 1]);
                        ffma2(acc, qb.x, w[4 * u + 2]);
                        ffma2(acc, qb.y, w[4 * u + 3]);
                    }
                    float2 sres = unpack2(acc);
                    oacc[lv][ch] += sres.x + sres.y;
                }
            }
        }
        __syncthreads();
    }

    // --- epilogue: folded BN + ReLU; thread owns half a voxel (32 ch) ---
    {
        int lv = t >> 1;
        int hh = t & 1;
        int i  = base + lv;
        if (i < m) {
            const float4* sc = (const float4*)(g_sc2 + hh * 32);
            const float4* sh = (const float4*)(g_sh2 + hh * 32);
            float4* dst = (float4*)(out + i * C2 + hh * 32);
#pragma unroll
            for (int j = 0; j < 8; j++) {
                float4 x = *(const float4*)&oacc[lv][hh * 32 + 4 * j];
                float4 s = __ldg(sc + j), o = __ldg(sh + j);
                float4 r;
                r.x = fmaxf(fmaf(x.x, s.x, o.x), 0.f);
                r.y = fmaxf(fmaf(x.y, s.y, o.y), 0.f);
                r.z = fmaxf(fmaf(x.z, s.z, o.z), 0.f);
                r.w = fmaxf(fmaf(x.w, s.w, o.w), 0.f);
                dst[j] = r;
            }
        }
    }
}

// Optional tail: if the harness flattens (f2, out_coors, batch_size) into d_out.
__global__ void tail_kernel(const int* __restrict__ ocoors,
                            const int* __restrict__ bs,
                            float* __restrict__ out,
                            int m, int extra) {
    int i = blockIdx.x * blockDim.x + threadIdx.x;
    if (i >= extra) return;
    float v;
    if (i < 4 * m)           v = (float)ocoors[i];
    else if (i == 4 * m)     v = (float)bs[0];
    else                     v = 0.0f;
    out[m * C2 + i] = v;
}

// ---------------- launch ----------------
extern "C" void kernel_launch(void* const* d_in, const int* in_sizes, int n_in,
                              void* d_out, int out_size) {
    const float* voxel_feat = (const float*)d_in[0];
    const int*   coors      = (const int*)  d_in[1];
    const int*   out_coors  = (const int*)  d_in[2];
    const float* W1 = (const float*)d_in[3];
    const float* g1 = (const float*)d_in[4];
    const float* b1 = (const float*)d_in[5];
    const float* m1 = (const float*)d_in[6];
    const float* v1 = (const float*)d_in[7];
    const float* W2 = (const float*)d_in[8];
    const float* g2 = (const float*)d_in[9];
    const float* b2 = (const float*)d_in[10];
    const float* m2 = (const float*)d_in[11];
    const float* v2 = (const float*)d_in[12];
    const int*   bs = (n_in > 13) ? (const int*)d_in[13] : nullptr;

    int n = in_sizes[0] / CIN;      // active input voxels
    int m = in_sizes[2] / 4;        // active output voxels
    float* out = (float*)d_out;

    reset_grid_kernel<<<(GRID_SZ / 4 + 255) / 256, 256>>>();
    scatter_kernel<<<(n + 255) / 256, 256>>>(coors, n);
    prep_w1_kernel<<<(27 * 8 * 32 + 255) / 256, 256>>>(W1, g1, b1, m1, v1);
    prep_w2_kernel<<<(27 * 16 * 64 + 255) / 256, 256>>>(W2, g2, b2, m2, v2);

    conv1_kernel<<<(n + 127) / 128, 256>>>(voxel_feat, coors, n);
    conv2_kernel<<<(m + 127) / 128, 256>>>(out_coors, out, m);

    int extra = out_size - m * C2;
    if (extra > 0 && bs != nullptr) {
        tail_kernel<<<(extra + 255) / 256, 256>>>(out_coors, bs, out, m, extra);
    }
}